// round 2
// baseline (speedup 1.0000x reference)
#include <cuda_runtime.h>

// LSTM_40948218200110: B=4096, T=1024, I=8, H=4 LSTM (PyTorch gate order) + FC[H->1].
// Strategy: 4 threads per batch element (one per hidden unit). Each thread computes
// its 4 gates (i,f,g,o for hidden unit k), updates c_k/h_k, and the 4-thread group
// exchanges h via shfl_xor each step. Recurrent weights are pre-permuted by (k^j)
// so shuffled values feed the dot product directly.

#define T_STEPS 1024
#define I_DIM   8

__device__ __forceinline__ float tanh_fast(float x) {
    float y;
    asm("tanh.approx.f32 %0, %1;" : "=f"(y) : "f"(x));
    return y;
}

// sigmoid(x) = 0.5 * tanh(0.5 x) + 0.5
__device__ __forceinline__ float sigmoid_fast(float x) {
    return fmaf(tanh_fast(0.5f * x), 0.5f, 0.5f);
}

__global__ __launch_bounds__(64) void lstm_kernel(
    const float* __restrict__ x,     // [B, T, I]
    const float* __restrict__ Wih,   // [16, 8]
    const float* __restrict__ Whh,   // [16, 4]
    const float* __restrict__ bih,   // [16]
    const float* __restrict__ bhh,   // [16]
    const float* __restrict__ fcw,   // [1, 4]
    const float* __restrict__ fcb,   // [1]
    float* __restrict__ out,         // [B, 1]
    int B)
{
    const int tid = blockIdx.x * 64 + threadIdx.x;
    const int b = tid >> 2;        // batch element
    const int k = tid & 3;         // hidden unit owned by this thread
    if (b >= B) return;

    // ---- Load input weights for this thread's 4 gates (rows k, 4+k, 8+k, 12+k) ----
    float wi[I_DIM], wf[I_DIM], wg[I_DIM], wo[I_DIM];
#pragma unroll
    for (int j = 0; j < I_DIM; j++) {
        wi[j] = Wih[(0  + k) * I_DIM + j];
        wf[j] = Wih[(4  + k) * I_DIM + j];
        wg[j] = Wih[(8  + k) * I_DIM + j];
        wo[j] = Wih[(12 + k) * I_DIM + j];
    }
    // ---- Recurrent weights, permuted: slot j corresponds to h from lane k^j ----
    //   slot 0: own h ; slot 1: shfl_xor(h,1) ; slot 2: shfl_xor(h,2) ; slot 3: shfl_xor(hx1,2)
    float ui[4], uf[4], ug[4], uo[4];
#pragma unroll
    for (int j = 0; j < 4; j++) {
        const int col = k ^ j;
        ui[j] = Whh[(0  + k) * 4 + col];
        uf[j] = Whh[(4  + k) * 4 + col];
        ug[j] = Whh[(8  + k) * 4 + col];
        uo[j] = Whh[(12 + k) * 4 + col];
    }
    const float bi = bih[0  + k] + bhh[0  + k];
    const float bf = bih[4  + k] + bhh[4  + k];
    const float bg = bih[8  + k] + bhh[8  + k];
    const float bo = bih[12 + k] + bhh[12 + k];

    const float4* xp = reinterpret_cast<const float4*>(x + (size_t)b * T_STEPS * I_DIM);

    float hs = 0.0f;               // own h_k
    float hx1 = 0.0f, hx2 = 0.0f, hx3 = 0.0f;  // h from lanes k^1, k^2, k^3
    float c = 0.0f;

#pragma unroll 4
    for (int t = 0; t < T_STEPS; t++) {
        // x[b,t,0:8] — all 4 lanes of the group read the same 32B (broadcast in L1)
        const float4 xa = xp[2 * t + 0];
        const float4 xb = xp[2 * t + 1];

        // ---- input-projection part (off the recurrent critical path) ----
        // two parallel partial chains per gate to shorten dependency
        float pi0 = fmaf(wi[0], xa.x, fmaf(wi[1], xa.y, fmaf(wi[2], xa.z, fmaf(wi[3], xa.w, bi))));
        float pi1 = fmaf(wi[4], xb.x, fmaf(wi[5], xb.y, fmaf(wi[6], xb.z,      wi[7] * xb.w)));
        float pf0 = fmaf(wf[0], xa.x, fmaf(wf[1], xa.y, fmaf(wf[2], xa.z, fmaf(wf[3], xa.w, bf))));
        float pf1 = fmaf(wf[4], xb.x, fmaf(wf[5], xb.y, fmaf(wf[6], xb.z,      wf[7] * xb.w)));
        float pg0 = fmaf(wg[0], xa.x, fmaf(wg[1], xa.y, fmaf(wg[2], xa.z, fmaf(wg[3], xa.w, bg))));
        float pg1 = fmaf(wg[4], xb.x, fmaf(wg[5], xb.y, fmaf(wg[6], xb.z,      wg[7] * xb.w)));
        float po0 = fmaf(wo[0], xa.x, fmaf(wo[1], xa.y, fmaf(wo[2], xa.z, fmaf(wo[3], xa.w, bo))));
        float po1 = fmaf(wo[4], xb.x, fmaf(wo[5], xb.y, fmaf(wo[6], xb.z,      wo[7] * xb.w)));

        float gi = pi0 + pi1;
        float gf = pf0 + pf1;
        float gg = pg0 + pg1;
        float go = po0 + po1;

        // ---- recurrent part (critical path: starts when h values are ready) ----
        gi = fmaf(ui[0], hs, fmaf(ui[1], hx1, fmaf(ui[2], hx2, fmaf(ui[3], hx3, gi))));
        gf = fmaf(uf[0], hs, fmaf(uf[1], hx1, fmaf(uf[2], hx2, fmaf(uf[3], hx3, gf))));
        gg = fmaf(ug[0], hs, fmaf(ug[1], hx1, fmaf(ug[2], hx2, fmaf(ug[3], hx3, gg))));
        go = fmaf(uo[0], hs, fmaf(uo[1], hx1, fmaf(uo[2], hx2, fmaf(uo[3], hx3, go))));

        const float is = sigmoid_fast(gi);
        const float fs = sigmoid_fast(gf);
        const float gt = tanh_fast(gg);
        const float os = sigmoid_fast(go);

        c = fmaf(fs, c, is * gt);
        hs = os * tanh_fast(c);

        // ---- exchange h within the 4-lane group ----
        hx1 = __shfl_xor_sync(0xffffffffu, hs, 1);
        hx2 = __shfl_xor_sync(0xffffffffu, hs, 2);
        hx3 = __shfl_xor_sync(0xffffffffu, hx1, 2);
    }

    // ---- final FC: out[b] = sum_k h_k * fcw[k] + fcb ----
    float v = hs * fcw[k];
    v += __shfl_xor_sync(0xffffffffu, v, 1);
    v += __shfl_xor_sync(0xffffffffu, v, 2);
    if (k == 0) out[b] = v + fcb[0];
}

extern "C" void kernel_launch(void* const* d_in, const int* in_sizes, int n_in,
                              void* d_out, int out_size)
{
    const float* x    = (const float*)d_in[0];
    const float* Wih  = (const float*)d_in[1];
    const float* Whh  = (const float*)d_in[2];
    const float* bih  = (const float*)d_in[3];
    const float* bhh  = (const float*)d_in[4];
    const float* fcw  = (const float*)d_in[5];
    const float* fcb  = (const float*)d_in[6];
    float* out = (float*)d_out;

    const int B = in_sizes[0] / (T_STEPS * I_DIM);   // 4096
    const int threads = B * 4;
    const int block = 64;
    const int grid = (threads + block - 1) / block;  // 256 blocks of 2 warps

    lstm_kernel<<<grid, block>>>(x, Wih, Whh, bih, bhh, fcw, fcb, out, B);
}

// round 3
// speedup vs baseline: 2.6839x; 2.6839x over previous
#include <cuda_runtime.h>

// LSTM_40948218200110: B=4096, T=1024, I=8, H=4 (PyTorch gate order) + FC[H->1].
// R3: latency-optimized scan. 4 threads per batch element (1 per hidden unit).
//  - All three h-exchanges are parallel shfl_xor (masks 1,2,3) — no serial shfl chain.
//  - sigmoid 0.5-prescale folded into weights/bias of i,f,o gates.
//  - Double-buffered register prefetch of x (4 steps per buffer) to hide DRAM latency.

#define T_STEPS 1024
#define I_DIM   8

__device__ __forceinline__ float tanh_fast(float x) {
    float y;
    asm("tanh.approx.f32 %0, %1;" : "=f"(y) : "f"(x));
    return y;
}

__global__ __launch_bounds__(64, 1) void lstm_kernel(
    const float* __restrict__ x,     // [B, T, I]
    const float* __restrict__ Wih,   // [16, 8]
    const float* __restrict__ Whh,   // [16, 4]
    const float* __restrict__ bih,   // [16]
    const float* __restrict__ bhh,   // [16]
    const float* __restrict__ fcw,   // [1, 4]
    const float* __restrict__ fcb,   // [1]
    float* __restrict__ out,         // [B, 1]
    int B)
{
    const int tid = blockIdx.x * 64 + threadIdx.x;
    const int b = tid >> 2;        // batch element
    const int k = tid & 3;         // hidden unit owned by this thread
    if (b >= B) return;

    // ---- Input weights for this thread's gates: rows k (i), 4+k (f), 8+k (g), 12+k (o).
    // i/f/o weights are pre-scaled by 0.5 so sigmoid(z) = 0.5*tanh(z_scaled)+0.5 needs no mul.
    float wi[I_DIM], wf[I_DIM], wg[I_DIM], wo[I_DIM];
#pragma unroll
    for (int j = 0; j < I_DIM; j++) {
        wi[j] = 0.5f * Wih[(0  + k) * I_DIM + j];
        wf[j] = 0.5f * Wih[(4  + k) * I_DIM + j];
        wg[j] =        Wih[(8  + k) * I_DIM + j];
        wo[j] = 0.5f * Wih[(12 + k) * I_DIM + j];
    }
    // ---- Recurrent weights, permuted: slot j multiplies h from lane k^j (shfl_xor mask j).
    float ui[4], uf[4], ug[4], uo[4];
#pragma unroll
    for (int j = 0; j < 4; j++) {
        const int col = k ^ j;
        ui[j] = 0.5f * Whh[(0  + k) * 4 + col];
        uf[j] = 0.5f * Whh[(4  + k) * 4 + col];
        ug[j] =        Whh[(8  + k) * 4 + col];
        uo[j] = 0.5f * Whh[(12 + k) * 4 + col];
    }
    const float bi = 0.5f * (bih[0  + k] + bhh[0  + k]);
    const float bf = 0.5f * (bih[4  + k] + bhh[4  + k]);
    const float bg =        (bih[8  + k] + bhh[8  + k]);
    const float bo = 0.5f * (bih[12 + k] + bhh[12 + k]);

    const float4* xp = reinterpret_cast<const float4*>(x + (size_t)b * T_STEPS * I_DIM);

    float hs = 0.0f;                              // own h_k
    float hx1 = 0.0f, hx2 = 0.0f, hx3 = 0.0f;     // h from lanes k^1, k^2, k^3
    float c = 0.0f;

    // One LSTM step given x[b,t,0:8] in (xa, xb).
    auto STEP = [&](float4 xa, float4 xb) {
        // x-projection (off the recurrent critical path; two parallel sub-chains per gate)
        float gi = fmaf(wi[0], xa.x, fmaf(wi[1], xa.y, fmaf(wi[2], xa.z, fmaf(wi[3], xa.w, bi))))
                 + fmaf(wi[4], xb.x, fmaf(wi[5], xb.y, fmaf(wi[6], xb.z, wi[7] * xb.w)));
        float gf = fmaf(wf[0], xa.x, fmaf(wf[1], xa.y, fmaf(wf[2], xa.z, fmaf(wf[3], xa.w, bf))))
                 + fmaf(wf[4], xb.x, fmaf(wf[5], xb.y, fmaf(wf[6], xb.z, wf[7] * xb.w)));
        float gg = fmaf(wg[0], xa.x, fmaf(wg[1], xa.y, fmaf(wg[2], xa.z, fmaf(wg[3], xa.w, bg))))
                 + fmaf(wg[4], xb.x, fmaf(wg[5], xb.y, fmaf(wg[6], xb.z, wg[7] * xb.w)));
        float go = fmaf(wo[0], xa.x, fmaf(wo[1], xa.y, fmaf(wo[2], xa.z, fmaf(wo[3], xa.w, bo))))
                 + fmaf(wo[4], xb.x, fmaf(wo[5], xb.y, fmaf(wo[6], xb.z, wo[7] * xb.w)));

        // Recurrent part. Own-h product starts immediately; cross terms wait on shfl results.
        gi = fmaf(ui[0], hs, gi);
        gf = fmaf(uf[0], hs, gf);
        gg = fmaf(ug[0], hs, gg);
        go = fmaf(uo[0], hs, go);
        gi = fmaf(ui[1], hx1, gi) + fmaf(ui[2], hx2, ui[3] * hx3);
        gf = fmaf(uf[1], hx1, gf) + fmaf(uf[2], hx2, uf[3] * hx3);
        gg = fmaf(ug[1], hx1, gg) + fmaf(ug[2], hx2, ug[3] * hx3);
        go = fmaf(uo[1], hx1, go) + fmaf(uo[2], hx2, uo[3] * hx3);

        const float is = fmaf(tanh_fast(gi), 0.5f, 0.5f);
        const float fs = fmaf(tanh_fast(gf), 0.5f, 0.5f);
        const float gt = tanh_fast(gg);
        const float os = fmaf(tanh_fast(go), 0.5f, 0.5f);

        c  = fmaf(fs, c, is * gt);
        hs = os * tanh_fast(c);

        // Parallel 3-way exchange (independent butterflies: masks 1, 2, 3)
        hx1 = __shfl_xor_sync(0xffffffffu, hs, 1);
        hx2 = __shfl_xor_sync(0xffffffffu, hs, 2);
        hx3 = __shfl_xor_sync(0xffffffffu, hs, 3);
    };

    // ---- Double-buffered register prefetch: each buffer holds 4 steps (8 float4) ----
    float4 A[8], B4[8];
#pragma unroll
    for (int j = 0; j < 8; j++) A[j]  = xp[j];          // steps 0..3
#pragma unroll
    for (int j = 0; j < 8; j++) B4[j] = xp[8 + j];      // steps 4..7

    for (int tt = 0; tt < T_STEPS; tt += 8) {
        // compute steps tt..tt+3 from A
#pragma unroll
        for (int s = 0; s < 4; s++) STEP(A[2 * s], A[2 * s + 1]);

        // refill A with steps tt+8..tt+11 (clamped; tail loads are redundant, unused)
        {
            const int t0 = (tt + 8 < T_STEPS) ? (tt + 8) : (T_STEPS - 4);
            const float4* p = xp + 2 * t0;
#pragma unroll
            for (int j = 0; j < 8; j++) A[j] = p[j];
        }

        // compute steps tt+4..tt+7 from B
#pragma unroll
        for (int s = 0; s < 4; s++) STEP(B4[2 * s], B4[2 * s + 1]);

        // refill B with steps tt+12..tt+15 (clamped)
        {
            const int t0 = (tt + 12 < T_STEPS) ? (tt + 12) : (T_STEPS - 4);
            const float4* p = xp + 2 * t0;
#pragma unroll
            for (int j = 0; j < 8; j++) B4[j] = p[j];
        }
    }

    // ---- final FC: out[b] = sum_k h_k * fcw[k] + fcb ----
    float v = hs * fcw[k];
    v += __shfl_xor_sync(0xffffffffu, v, 1);
    v += __shfl_xor_sync(0xffffffffu, v, 2);
    if (k == 0) out[b] = v + fcb[0];
}

extern "C" void kernel_launch(void* const* d_in, const int* in_sizes, int n_in,
                              void* d_out, int out_size)
{
    const float* x    = (const float*)d_in[0];
    const float* Wih  = (const float*)d_in[1];
    const float* Whh  = (const float*)d_in[2];
    const float* bih  = (const float*)d_in[3];
    const float* bhh  = (const float*)d_in[4];
    const float* fcw  = (const float*)d_in[5];
    const float* fcb  = (const float*)d_in[6];
    float* out = (float*)d_out;

    const int B = in_sizes[0] / (T_STEPS * I_DIM);   // 4096
    const int threads = B * 4;
    const int block = 64;
    const int grid = (threads + block - 1) / block;

    lstm_kernel<<<grid, block>>>(x, Wih, Whh, bih, bhh, fcw, fcb, out, B);
}